// round 2
// baseline (speedup 1.0000x reference)
#include <cuda_runtime.h>
#include <cstdint>

#define N_NODES 100000
#define N_EDGES 1600000
#define N_GRAPHS 512

// ---------------- scratch (device globals; no allocation allowed) ----------
__device__ float g_deg[N_NODES];
__device__ float g_dis[N_NODES];
__device__ float g_h1[N_NODES * 32];
__device__ float g_agg1[N_NODES * 32];   // becomes out1 in-place after fuse1
__device__ float g_h2[N_NODES * 32];
__device__ float g_agg2[N_NODES * 32];
__device__ float g_norm[N_EDGES];
__device__ int   g_src[N_EDGES];
__device__ int   g_dst[N_EDGES];
__device__ float g_gsum[N_GRAPHS];
__device__ float g_gcnt[N_GRAPHS];
__device__ int   g_is64;

// ---------------- f32x2 helpers (Blackwell packed FFMA) ---------------------
__device__ __forceinline__ unsigned long long pack2(float x) {
    unsigned long long r;
    asm("mov.b64 %0, {%1, %1};" : "=l"(r) : "r"(__float_as_uint(x)));
    return r;
}
__device__ __forceinline__ void ffma2(unsigned long long& d,
                                      unsigned long long a,
                                      unsigned long long b) {
    asm("fma.rn.f32x2 %0, %1, %2, %0;" : "+l"(d) : "l"(a), "l"(b));
}

// ---------------- dtype detection ------------------------------------------
// If edge_index is really int64, every u64-read value is < N_NODES.
// If it is int32, reads combine two random node ids -> almost surely >= 2^32.
__global__ void detect_kernel(const void* ei) {
    __shared__ int bad;
    if (threadIdx.x == 0) bad = 0;
    __syncthreads();
    const unsigned long long* p = (const unsigned long long*)ei;
    for (int i = threadIdx.x; i < 1024; i += 256)
        if (p[i] >= (unsigned long long)N_NODES) bad = 1;
    __syncthreads();
    if (threadIdx.x == 0) g_is64 = bad ? 0 : 1;
}

// ---------------- zero init ------------------------------------------------
__global__ void zero_kernel() {
    int i = blockIdx.x * 256 + threadIdx.x;
    if (i < N_NODES * 32) { g_agg1[i] = 0.f; g_agg2[i] = 0.f; }
    if (i < N_NODES) g_deg[i] = 0.f;
    if (i < N_GRAPHS) { g_gsum[i] = 0.f; g_gcnt[i] = 0.f; }
}

// ---------------- edge prep: convert indices + degree count ----------------
__global__ void prep_kernel(const void* ei) {
    int e = blockIdx.x * 256 + threadIdx.x;
    if (e >= N_EDGES) return;
    int s, d;
    if (g_is64) {
        const long long* p = (const long long*)ei;
        s = (int)p[e]; d = (int)p[N_EDGES + e];
    } else {
        const int* p = (const int*)ei;
        s = p[e]; d = p[N_EDGES + e];
    }
    // clamp as crash insurance
    s = min(max(s, 0), N_NODES - 1);
    d = min(max(d, 0), N_NODES - 1);
    g_src[e] = s; g_dst[e] = d;
    atomicAdd(&g_deg[d], 1.0f);
}

__global__ void dis_kernel() {
    int i = blockIdx.x * 256 + threadIdx.x;
    if (i < N_NODES) g_dis[i] = rsqrtf(g_deg[i] + 1.0f);
}

__global__ void norm_kernel() {
    int e = blockIdx.x * 256 + threadIdx.x;
    if (e < N_EDGES) g_norm[e] = g_dis[g_src[e]] * g_dis[g_dst[e]];
}

// ---------------- GEMM: h[n][0:32] = x[n][0:K] @ W[K][32] ------------------
// LAYER selects scratch arrays INSIDE device code (host must never pass
// __device__ symbols as arguments — host shadow address is invalid!)
template <int KDIM, int LAYER>
__global__ void gemm_kernel(const float* __restrict__ xin,
                            const float* __restrict__ W) {
    const float* x = (LAYER == 1) ? xin : (const float*)g_agg1;
    float* h = (LAYER == 1) ? g_h1 : g_h2;

    __shared__ float Ws[KDIM * 32];
    for (int i = threadIdx.x; i < KDIM * 8; i += 128)
        ((float4*)Ws)[i] = ((const float4*)W)[i];
    __syncthreads();
    int node = blockIdx.x * 128 + threadIdx.x;
    if (node >= N_NODES) return;

    unsigned long long acc[16];
#pragma unroll
    for (int p = 0; p < 16; p++) acc[p] = 0ULL;

    const float4* xrow = (const float4*)(x + (size_t)node * KDIM);
#pragma unroll 4
    for (int k4 = 0; k4 < KDIM / 4; k4++) {
        float4 xv = xrow[k4];
        float xs[4] = {xv.x, xv.y, xv.z, xv.w};
#pragma unroll
        for (int j = 0; j < 4; j++) {
            unsigned long long xp = pack2(xs[j]);
            const ulonglong2* wr = (const ulonglong2*)(Ws + (k4 * 4 + j) * 32);
#pragma unroll
            for (int q = 0; q < 8; q++) {
                ulonglong2 ww = wr[q];
                ffma2(acc[2 * q],     xp, ww.x);
                ffma2(acc[2 * q + 1], xp, ww.y);
            }
        }
    }
    ulonglong2* outp = (ulonglong2*)(h + (size_t)node * 32);
#pragma unroll
    for (int q = 0; q < 8; q++) {
        ulonglong2 t; t.x = acc[2 * q]; t.y = acc[2 * q + 1];
        outp[q] = t;
    }
}

// ---------------- edge scatter: agg[dst] += h[src] * norm ------------------
// 8 lanes per edge -> per warp: 4 contiguous 128B gathers + 4x 128B vec atomics
template <int LAYER>
__global__ void scatter_kernel() {
    const float* h = (LAYER == 1) ? g_h1 : g_h2;
    float* agg = (LAYER == 1) ? g_agg1 : g_agg2;

    int idx = blockIdx.x * 256 + threadIdx.x;
    int e = idx >> 3;
    if (e >= N_EDGES) return;
    int c = idx & 7;
    float n = g_norm[e];
    int s = g_src[e], d = g_dst[e];
    float4 v = ((const float4*)(h + (size_t)s * 32))[c];
    float* p = agg + (size_t)d * 32 + c * 4;
    asm volatile("red.global.add.v4.f32 [%0], {%1,%2,%3,%4};"
                 :: "l"(p), "f"(v.x * n), "f"(v.y * n), "f"(v.z * n), "f"(v.w * n)
                 : "memory");
}

// ---------------- fuse: out1 = relu(agg1 + h1*dis^2 + b1) (in place) -------
__global__ void fuse1_kernel(const float* __restrict__ b1) {
    int idx = blockIdx.x * 256 + threadIdx.x;
    if (idx >= N_NODES * 8) return;
    int n = idx >> 3, c = idx & 7;
    float dd = g_dis[n]; float d2 = dd * dd;
    float4 a = ((float4*)g_agg1)[idx];
    float4 hv = ((const float4*)g_h1)[idx];
    float4 b = ((const float4*)b1)[c];
    a.x = fmaxf(fmaf(hv.x, d2, a.x) + b.x, 0.f);
    a.y = fmaxf(fmaf(hv.y, d2, a.y) + b.y, 0.f);
    a.z = fmaxf(fmaf(hv.z, d2, a.z) + b.z, 0.f);
    a.w = fmaxf(fmaf(hv.w, d2, a.w) + b.w, 0.f);
    ((float4*)g_agg1)[idx] = a;
}

// ---------------- pool: fold relu2 + dot(Wo) + segment mean-sum ------------
__global__ void pool_kernel(const void* batch,
                            const float* __restrict__ b2,
                            const float* __restrict__ Wo) {
    int n = blockIdx.x * 256 + threadIdx.x;
    if (n >= N_NODES) return;
    int g;
    if (g_is64) g = (int)((const long long*)batch)[n];
    else        g = ((const int*)batch)[n];
    g = min(max(g, 0), N_GRAPHS - 1);
    float dd = g_dis[n]; float d2 = dd * dd;
    const float4* a2 = (const float4*)(g_agg2 + (size_t)n * 32);
    const float4* hh = (const float4*)(g_h2 + (size_t)n * 32);
    float s = 0.f;
#pragma unroll
    for (int c = 0; c < 8; c++) {
        float4 a = a2[c], h = hh[c];
        float4 b = ((const float4*)b2)[c];
        float4 w = ((const float4*)Wo)[c];
        s += fmaxf(fmaf(h.x, d2, a.x) + b.x, 0.f) * w.x;
        s += fmaxf(fmaf(h.y, d2, a.y) + b.y, 0.f) * w.y;
        s += fmaxf(fmaf(h.z, d2, a.z) + b.z, 0.f) * w.z;
        s += fmaxf(fmaf(h.w, d2, a.w) + b.w, 0.f) * w.w;
    }
    atomicAdd(&g_gsum[g], s);
    atomicAdd(&g_gcnt[g], 1.0f);
}

__global__ void final_kernel(float* __restrict__ out,
                             const float* __restrict__ bo) {
    int i = blockIdx.x * 256 + threadIdx.x;
    if (i < N_GRAPHS)
        out[i] = g_gsum[i] / fmaxf(g_gcnt[i], 1.0f) + bo[0];
}

// ---------------- launch ----------------------------------------------------
extern "C" void kernel_launch(void* const* d_in, const int* in_sizes, int n_in,
                              void* d_out, int out_size) {
    const float* x   = (const float*)d_in[0];
    const void*  ei  = d_in[1];
    const void*  bat = d_in[2];
    const float* W1  = (const float*)d_in[3];
    const float* b1  = (const float*)d_in[4];
    const float* W2  = (const float*)d_in[5];
    const float* b2  = (const float*)d_in[6];
    const float* Wo  = (const float*)d_in[7];
    const float* bo  = (const float*)d_in[8];
    float* out = (float*)d_out;

    detect_kernel<<<1, 256>>>(ei);
    zero_kernel<<<(N_NODES * 32 + 255) / 256, 256>>>();
    prep_kernel<<<(N_EDGES + 255) / 256, 256>>>(ei);
    dis_kernel<<<(N_NODES + 255) / 256, 256>>>();
    norm_kernel<<<(N_EDGES + 255) / 256, 256>>>();

    // layer 1
    gemm_kernel<128, 1><<<(N_NODES + 127) / 128, 128>>>(x, W1);
    scatter_kernel<1><<<(N_EDGES * 8 + 255) / 256, 256>>>();
    fuse1_kernel<<<(N_NODES * 8 + 255) / 256, 256>>>(b1);

    // layer 2
    gemm_kernel<32, 2><<<(N_NODES + 127) / 128, 128>>>(nullptr, W2);
    scatter_kernel<2><<<(N_EDGES * 8 + 255) / 256, 256>>>();

    // pooling + head
    pool_kernel<<<(N_NODES + 255) / 256, 256>>>(bat, b2, Wo);
    final_kernel<<<2, 256>>>(out, bo);
}